// round 1
// baseline (speedup 1.0000x reference)
#include <cuda_runtime.h>
#include <math.h>

#define Bb 4
#define Nn 5
#define Kk 5
#define Qq 5
#define Ll 128
#define Ff 768
#define NQc (Nn*Qq)          // 25
#define BQ (Bb*NQc)          // 100
#define EPSc 1e-8f

// ---------------- scratch (device globals; no allocation allowed) ----------
__device__ float g_pnum[Bb*Nn*4*Ff];     // class prototype accumulators
__device__ float g_proto[Bb*Nn*4*Ff];    // finalized prototypes
__device__ float g_den[Bb*Nn*4];
__device__ float g_p2[Bb*Nn*4];
__device__ float g_sproto[Bb*Nn*Ff];     // sentence prototypes
__device__ int   g_spred[BQ];
__device__ float g_sloss;
__device__ float g_bce[BQ];
__device__ float g_perex[BQ];
__device__ unsigned long long g_amax[BQ*4];

// ---------------- helpers --------------------------------------------------
__device__ __forceinline__ float dot4(float4 a, float4 b) {
    return a.x*b.x + a.y*b.y + a.z*b.z + a.w*b.w;
}
__device__ __forceinline__ unsigned long long enc_key(float v, int l) {
    unsigned u = __float_as_uint(v);
    u = (u & 0x80000000u) ? ~u : (u | 0x80000000u);
    return ((unsigned long long)u << 32) | (unsigned long long)(0xFFFFFFFFu - (unsigned)l);
}

// ---------------- 1. init scratch ------------------------------------------
__global__ void k_init() {
    int i = blockIdx.x * blockDim.x + threadIdx.x;
    if (i < Bb*Nn*4*Ff) g_pnum[i] = 0.f;
    if (i < Bb*Nn*4)    g_den[i]  = 0.f;
    if (i < BQ)         g_bce[i]  = 0.f;
    if (i < BQ*4)       g_amax[i] = 0ull;
    if (i == 0)         g_sloss   = 0.f;
}

// ---------------- 2. sentence prototypes (mean over K of l=0 slice) --------
__global__ void k_sproto(const float* __restrict__ sup) {
    int bn = blockIdx.x;            // 0..19
    int f  = threadIdx.x;           // 0..767
    float s = 0.f;
    #pragma unroll
    for (int k = 0; k < Kk; k++)
        s += sup[((size_t)(bn*Kk + k) * Ll) * Ff + f];
    g_sproto[bn*Ff + f] = s * (1.f/Kk);
}

// ---------------- 3. class prototype accumulation --------------------------
// grid: (B*N*K, 4 L-chunks of 32), 256 threads, 3 f-values per thread
__global__ void k_accum(const float* __restrict__ sup,
                        const int* __restrict__ sem,
                        const int* __restrict__ sam) {
    int bnk = blockIdx.x;
    int bn  = bnk / Kk;
    int l0  = blockIdx.y * 32;
    int tid = threadIdx.x;

    __shared__ int slab[32];
    if (tid < 32) {
        int l   = l0 + tid;
        int lab = sem[bnk*Ll + l];
        int att = sam[bnk*Ll + l];
        slab[tid] = (att > 0 && lab >= 1 && lab <= 4) ? (lab - 1) : -1;
    }
    __syncthreads();

    float a00=0,a01=0,a02=0, a10=0,a11=0,a12=0, a20=0,a21=0,a22=0, a30=0,a31=0,a32=0;
    const float* base = sup + (size_t)bnk * Ll * Ff + (size_t)l0 * Ff;

    for (int i = 0; i < 32; i++) {
        int c = slab[i];                 // uniform across block
        if (c < 0) continue;             // skip unlabeled rows entirely
        float v0 = base[i*Ff +       tid];
        float v1 = base[i*Ff + 256 + tid];
        float v2 = base[i*Ff + 512 + tid];
        if      (c == 0) { a00+=v0; a01+=v1; a02+=v2; }
        else if (c == 1) { a10+=v0; a11+=v1; a12+=v2; }
        else if (c == 2) { a20+=v0; a21+=v1; a22+=v2; }
        else             { a30+=v0; a31+=v1; a32+=v2; }
    }

    float* pn = g_pnum + (size_t)bn * 4 * Ff;
    atomicAdd(pn + 0*Ff +       tid, a00);
    atomicAdd(pn + 0*Ff + 256 + tid, a01);
    atomicAdd(pn + 0*Ff + 512 + tid, a02);
    atomicAdd(pn + 1*Ff +       tid, a10);
    atomicAdd(pn + 1*Ff + 256 + tid, a11);
    atomicAdd(pn + 1*Ff + 512 + tid, a12);
    atomicAdd(pn + 2*Ff +       tid, a20);
    atomicAdd(pn + 2*Ff + 256 + tid, a21);
    atomicAdd(pn + 2*Ff + 512 + tid, a22);
    atomicAdd(pn + 3*Ff +       tid, a30);
    atomicAdd(pn + 3*Ff + 256 + tid, a31);
    atomicAdd(pn + 3*Ff + 512 + tid, a32);

    if (tid < 4) {
        int cnt = 0;
        for (int i = 0; i < 32; i++) if (slab[i] == tid) cnt++;
        if (cnt) atomicAdd(&g_den[bn*4 + tid], (float)cnt);
    }
}

// ---------------- 4. prototype finalize: divide + p2 ------------------------
__global__ void k_protofin() {
    int bnc = blockIdx.x;               // 0..79
    int tid = threadIdx.x;              // 256
    float den = g_den[bnc] + EPSc;
    float inv = 1.f / den;
    float p2 = 0.f;
    #pragma unroll
    for (int j = 0; j < 3; j++) {
        int idx = bnc*Ff + j*256 + tid;
        float p = g_pnum[idx] * inv;
        g_proto[idx] = p;
        p2 += p * p;
    }
    __shared__ float red[256];
    red[tid] = p2; __syncthreads();
    for (int s = 128; s > 0; s >>= 1) {
        if (tid < s) red[tid] += red[tid + s];
        __syncthreads();
    }
    if (tid == 0) g_p2[bnc] = red[0];
}

// ---------------- 5. sentence logits / loss / pred --------------------------
__global__ void k_sent(const float* __restrict__ qemb,
                       const int* __restrict__ slabel) {
    int bq  = blockIdx.x;               // 0..99
    int b   = bq / NQc;
    int tid = threadIdx.x;              // 128
    const float* qrow = qemb + (size_t)bq * Ll * Ff;   // l=0 slice
    float qv[6];
    #pragma unroll
    for (int j = 0; j < 6; j++) qv[j] = qrow[tid + j*128];

    float d[Nn];
    #pragma unroll
    for (int n = 0; n < Nn; n++) {
        float s = 0.f;
        #pragma unroll
        for (int j = 0; j < 6; j++) {
            float dd = g_sproto[(b*Nn + n)*Ff + tid + j*128] - qv[j];
            s += dd * dd;
        }
        d[n] = s;
    }
    __shared__ float red[128];
    __shared__ float sdist[Nn];
    for (int n = 0; n < Nn; n++) {
        red[tid] = d[n]; __syncthreads();
        for (int s = 64; s > 0; s >>= 1) {
            if (tid < s) red[tid] += red[tid + s];
            __syncthreads();
        }
        if (tid == 0) sdist[n] = red[0];
        __syncthreads();
    }
    if (tid == 0) {
        float lg[Nn];
        float mx = -1e30f;
        int pred = 0;
        #pragma unroll
        for (int n = 0; n < Nn; n++) {
            lg[n] = -sdist[n];
            if (lg[n] > mx) { mx = lg[n]; pred = n; }
        }
        float se = 0.f;
        #pragma unroll
        for (int n = 0; n < Nn; n++) se += expf(lg[n] - mx);
        float lse = mx + logf(se);
        int lab = slabel[bq];
        float logp = lg[lab] - lse;
        atomicAdd(&g_sloss, -logp * (1.f / BQ));
        g_spred[bq] = pred;
    }
}

// ---------------- 6. main: token logits + BCE + argmax ----------------------
// grid (BQ, 16), 256 threads = 8 warps; warp w handles l = by*8 + w
__global__ void k_main(const float* __restrict__ qemb,
                       const int* __restrict__ qem,
                       const int* __restrict__ qatt_in,
                       const int* __restrict__ slabel) {
    int bq   = blockIdx.x;
    int b    = bq / NQc;
    int tid  = threadIdx.x;
    int w    = tid >> 5;
    int lane = tid & 31;
    int l    = blockIdx.y * 8 + w;
    int cond = slabel[bq];

    __shared__ float sp[4*Ff];          // 12 KB: 4 prototypes
    __shared__ float sp2[4];
    const float* pb = g_proto + (size_t)(b*Nn + cond) * 4 * Ff;
    for (int i = tid; i < 4*Ff; i += 256) sp[i] = pb[i];
    if (tid < 4) sp2[tid] = g_p2[(b*Nn + cond)*4 + tid];
    __syncthreads();

    const float4* q4 = (const float4*)(qemb + ((size_t)bq * Ll + l) * Ff);
    const float4* p0 = (const float4*)(sp + 0*Ff);
    const float4* p1 = (const float4*)(sp + 1*Ff);
    const float4* p2v = (const float4*)(sp + 2*Ff);
    const float4* p3 = (const float4*)(sp + 3*Ff);

    float q2 = 0.f, s0 = 0.f, s1 = 0.f, s2 = 0.f, s3 = 0.f;
    #pragma unroll
    for (int j = 0; j < 6; j++) {
        float4 qv = q4[lane + j*32];
        q2 += dot4(qv, qv);
        s0 += dot4(qv, p0[lane + j*32]);
        s1 += dot4(qv, p1[lane + j*32]);
        s2 += dot4(qv, p2v[lane + j*32]);
        s3 += dot4(qv, p3[lane + j*32]);
    }
    #pragma unroll
    for (int off = 16; off; off >>= 1) {
        q2 += __shfl_xor_sync(0xffffffffu, q2, off);
        s0 += __shfl_xor_sync(0xffffffffu, s0, off);
        s1 += __shfl_xor_sync(0xffffffffu, s1, off);
        s2 += __shfl_xor_sync(0xffffffffu, s2, off);
        s3 += __shfl_xor_sync(0xffffffffu, s3, off);
    }

    __shared__ float sbce[8];
    __shared__ unsigned long long skey[8][4];
    if (lane == 0) {
        float qatt = (float)qatt_in[bq*Ll + l];
        int   tlab = qem[bq*Ll + l];
        float qp[4] = { s0, s1, s2, s3 };
        float bcesum = 0.f;
        #pragma unroll
        for (int c = 0; c < 4; c++) {
            float x = -(q2 + sp2[c] - 2.f * qp[c]);
            float t = (tlab == c + 1) ? 1.f : 0.f;
            bcesum += fmaxf(x, 0.f) - x * t + log1pf(expf(-fabsf(x)));
            float m = x - 1000.f * (1.f - qatt);
            skey[w][c] = enc_key(m, l);
        }
        sbce[w] = bcesum * qatt;
    }
    __syncthreads();
    if (tid < 4) {
        unsigned long long mk = skey[0][tid];
        #pragma unroll
        for (int i = 1; i < 8; i++) if (skey[i][tid] > mk) mk = skey[i][tid];
        atomicMax(&g_amax[bq*4 + tid], mk);
    }
    if (tid == 0) {
        float s = 0.f;
        #pragma unroll
        for (int i = 0; i < 8; i++) s += sbce[i];
        atomicAdd(&g_bce[bq], s);
    }
}

// ---------------- 7. per-example finalize + final_pred ----------------------
__global__ void k_finpred(const int* __restrict__ qatt_in,
                          float* __restrict__ out) {
    int bq  = blockIdx.x;
    int l   = threadIdx.x;              // 128
    float qatt = (float)qatt_in[bq*Ll + l];

    __shared__ float red[128];
    red[l] = qatt; __syncthreads();
    for (int s = 64; s > 0; s >>= 1) {
        if (l < s) red[l] += red[l + s];
        __syncthreads();
    }
    __shared__ float sper;
    __shared__ int si[4];
    if (l == 0) {
        sper = g_bce[bq] / (red[0] * 4.f + EPSc);
        g_perex[bq] = sper;
    }
    if (l < 4)
        si[l] = (int)(0xFFFFFFFFu - (unsigned)(g_amax[bq*4 + l] & 0xFFFFFFFFull));
    __syncthreads();

    int i0 = si[0], i1 = si[1], i2 = si[2], i3 = si[3];
    int p = 0;
    if (l == i0)            p = 1;
    if (l > i0 && l <= i1)  p = 2;
    if (l == i2)            p = 3;
    if (l > i2 && l <= i3)  p = 4;
    int sp = g_spred[bq];
    int fp = (p != 0) ? (4*sp + p) : 0;
    out[1 + bq*Ll + l] = (float)fp;
}

// ---------------- 8. final loss ---------------------------------------------
__global__ void k_loss(float* __restrict__ out) {
    int tid = threadIdx.x;              // 128
    float s = 0.f;
    for (int i = tid; i < BQ; i += 128) s += g_perex[i];
    __shared__ float red[128];
    red[tid] = s; __syncthreads();
    for (int st = 64; st > 0; st >>= 1) {
        if (tid < st) red[tid] += red[tid + st];
        __syncthreads();
    }
    if (tid == 0) out[0] = g_sloss + red[0] * (1.f / BQ);
}

// ---------------- launch ----------------------------------------------------
extern "C" void kernel_launch(void* const* d_in, const int* in_sizes, int n_in,
                              void* d_out, int out_size) {
    const float* sup    = (const float*)d_in[0];
    const float* qemb   = (const float*)d_in[1];
    const int*   sem    = (const int*)d_in[2];
    const int*   qem    = (const int*)d_in[3];
    const int*   sam    = (const int*)d_in[4];
    const int*   qatt   = (const int*)d_in[5];
    const int*   slabel = (const int*)d_in[6];
    float* out = (float*)d_out;

    k_init<<<(Bb*Nn*4*Ff + 255)/256, 256>>>();
    k_sproto<<<Bb*Nn, Ff>>>(sup);
    {
        dim3 g(Bb*Nn*Kk, 4);
        k_accum<<<g, 256>>>(sup, sem, sam);
    }
    k_protofin<<<Bb*Nn*4, 256>>>();
    k_sent<<<BQ, 128>>>(qemb, slabel);
    {
        dim3 g(BQ, 16);
        k_main<<<g, 256>>>(qemb, qem, qatt, slabel);
    }
    k_finpred<<<BQ, 128>>>(qatt, out);
    k_loss<<<1, 128>>>(out);
}